// round 8
// baseline (speedup 1.0000x reference)
#include <cuda_runtime.h>
#include <cstdint>

#define N_FFT 8192
#define NT    512
#define D_CH  512
#define SEQ   4096
#define NBATCH 4

// Padded smem index: +1 float2 every 16
#define PADI(i) ((i) + ((i) >> 4))
#define BUFSZ (N_FFT + (N_FFT >> 4))   // 8704 float2 = 69632 B

__device__ float2 g_tw[N_FFT];                          // exp(-2*pi*i*k/N)
__device__ float2 g_tfft[(size_t)D_CH * N_FFT];         // t spectra, scrambled [d][g*512+t]
__device__ float  g_xT[(size_t)NBATCH * D_CH * SEQ];
__device__ float  g_tT[(size_t)D_CH * 2 * SEQ];
__device__ float  g_oT[(size_t)NBATCH * D_CH * SEQ];

__device__ __forceinline__ float2 cadd(float2 a, float2 b) { return make_float2(a.x + b.x, a.y + b.y); }
__device__ __forceinline__ float2 csub(float2 a, float2 b) { return make_float2(a.x - b.x, a.y - b.y); }
__device__ __forceinline__ float2 cmul(float2 a, float2 b) {
    return make_float2(a.x * b.x - a.y * b.y, a.x * b.y + a.y * b.x);
}
__device__ __forceinline__ float2 conjf2(float2 a) { return make_float2(a.x, -a.y); }

template <bool INV>
__device__ __forceinline__ float2 mulJ(float2 z) {
    return INV ? make_float2(-z.y, z.x) : make_float2(z.y, -z.x);
}
template <bool INV>
__device__ __forceinline__ float2 twc(float2 z, float re, float im) {
    float2 w = make_float2(re, INV ? -im : im);
    return cmul(z, w);
}

template <bool INV>
__device__ __forceinline__ void dft4(float2& a0, float2& a1, float2& a2, float2& a3) {
    float2 t0 = cadd(a0, a2), t1 = csub(a0, a2);
    float2 t2 = cadd(a1, a3), t3 = mulJ<INV>(csub(a1, a3));
    a0 = cadd(t0, t2);
    a1 = cadd(t1, t3);
    a2 = csub(t0, t2);
    a3 = csub(t1, t3);
}

// 16-point DFT: y[r] = sum_j a[j] * w16^{(-/+)rj}; output y[r] lands at a[SW16[r]]
template <bool INV>
__device__ __forceinline__ void dft16(float2 a[16]) {
    const float C1 = 0.92387953251128675613f;
    const float S1 = 0.38268343236508977173f;
    const float H  = 0.70710678118654752440f;
#pragma unroll
    for (int ji = 0; ji < 4; ji++) dft4<INV>(a[ji], a[ji + 4], a[ji + 8], a[ji + 12]);
    a[5]  = twc<INV>(a[5],  C1, -S1);
    a[9]  = twc<INV>(a[9],   H,  -H);
    a[13] = twc<INV>(a[13], S1, -C1);
    a[6]  = twc<INV>(a[6],   H,  -H);
    a[10] = mulJ<INV>(a[10]);
    a[14] = twc<INV>(a[14], -H,  -H);
    a[7]  = twc<INV>(a[7],  S1, -C1);
    a[11] = twc<INV>(a[11], -H,  -H);
    a[15] = twc<INV>(a[15], -C1, S1);
#pragma unroll
    for (int ro = 0; ro < 4; ro++) dft4<INV>(a[4 * ro], a[4 * ro + 1], a[4 * ro + 2], a[4 * ro + 3]);
}

// cos/sin(pi*g/16) tables (compile-time folded under full unroll)
#define DEF_C32 constexpr float C32[16] = { \
    1.0f, 0.98078528040323044913f, 0.92387953251128675613f, 0.83146961230254523708f, \
    0.70710678118654752440f, 0.55557023301960222474f, 0.38268343236508977173f, 0.19509032201612826785f, \
    0.0f, -0.19509032201612826785f, -0.38268343236508977173f, -0.55557023301960222474f, \
    -0.70710678118654752440f, -0.83146961230254523708f, -0.92387953251128675613f, -0.98078528040323044913f }
#define DEF_S32 constexpr float S32[16] = { \
    0.0f, 0.19509032201612826785f, 0.38268343236508977173f, 0.55557023301960222474f, \
    0.70710678118654752440f, 0.83146961230254523708f, 0.92387953251128675613f, 0.98078528040323044913f, \
    1.0f, 0.98078528040323044913f, 0.92387953251128675613f, 0.83146961230254523708f, \
    0.70710678118654752440f, 0.55557023301960222474f, 0.38268343236508977173f, 0.19509032201612826785f }

#define SW16_DEF constexpr int SW16[16] = {0,4,8,12, 1,5,9,13, 2,6,10,14, 3,7,11,15}

// Forward stages A + E1 + B + E2 + C1 + C2.
// Input: a[n1] logical (x[t+512*n1]). Output: cv[SW16[g]] = X[k1+16c+256g+4096j], scrambled.
// Uses X smem buffer; leaves no pending sync requirement (last op is the C read).
__device__ __forceinline__ void fwd8192(float2* __restrict__ X, float2 a[16], float2 cv[16], int t) {
    SW16_DEF; DEF_C32; DEF_S32;
    const int k1 = t >> 5, m = t & 31;
    const int cc = (t & 31) >> 1, jj = t & 1;
    // Stage A: dft16 over n1, twiddle w^{t*k1}, write smem[k1r*512 + t]
    dft16<false>(a);
    {
        float2 w1 = g_tw[t], w8 = g_tw[8 * t];
        X[PADI(t)] = a[SW16[0]];
        float2 w = w1;
#pragma unroll
        for (int r = 1; r < 8; r++) { X[PADI(r * 512 + t)] = cmul(a[SW16[r]], w); w = cmul(w, w1); }
        X[PADI(8 * 512 + t)] = cmul(a[SW16[8]], w8);
        w = cmul(w8, w1);
#pragma unroll
        for (int r = 9; r < 16; r++) { X[PADI(r * 512 + t)] = cmul(a[SW16[r]], w); w = cmul(w, w1); }
    }
    __syncthreads();
    // Stage B: per (k1,m) gather stride 32, dft16 over w, twiddle w512^{m*c}, write [k1*512+32c+m]
    {
        float2 b[16];
#pragma unroll
        for (int r = 0; r < 16; r++) b[r] = X[PADI(k1 * 512 + m + 32 * r)];
        dft16<false>(b);
        float2 w1 = g_tw[16 * m], w8 = g_tw[128 * m];
        __syncthreads();  // all reads done before in-place writes
        X[PADI(k1 * 512 + m)] = b[SW16[0]];
        float2 w = w1;
#pragma unroll
        for (int r = 1; r < 8; r++) { X[PADI(k1 * 512 + 32 * r + m)] = cmul(b[SW16[r]], w); w = cmul(w, w1); }
        X[PADI(k1 * 512 + 32 * 8 + m)] = cmul(b[SW16[8]], w8);
        w = cmul(w8, w1);
#pragma unroll
        for (int r = 9; r < 16; r++) { X[PADI(k1 * 512 + 32 * r + m)] = cmul(b[SW16[r]], w); w = cmul(w, w1); }
    }
    __syncthreads();
    // Stage C1: per (k1,c,j) gather stride 2, dft16 over h
#pragma unroll
    for (int h = 0; h < 16; h++) cv[h] = X[PADI(k1 * 512 + 32 * cc + jj + 2 * h)];
    dft16<false>(cv);
    // Stage C2: radix-2 across lane pairs via shfl; w32^g compile-time.
#pragma unroll
    for (int g = 0; g < 16; g++) {
        float2 v = cv[SW16[g]];
        float2 send = (jj == 1) ? cmul(v, make_float2(C32[g], -S32[g])) : v;
        float2 recv;
        recv.x = __shfl_xor_sync(0xffffffffu, send.x, 1);
        recv.y = __shfl_xor_sync(0xffffffffu, send.y, 1);
        cv[SW16[g]] = (jj == 0) ? cadd(v, recv) : csub(recv, send);
    }
}

// ---------------------------------------------------------------------------
__global__ void ker_tw() {
    int k = blockIdx.x * blockDim.x + threadIdx.x;
    if (k < N_FFT) {
        float s, c;
        sincospif(-2.0f * (float)k / (float)N_FFT, &s, &c);
        g_tw[k] = make_float2(c, s);
    }
}

// float4 tiled transpose: in[b][r][c] -> out[b][c][r]. 64x64 float tiles, 256 threads.
__global__ void __launch_bounds__(256) ker_T4(const float* __restrict__ in, float* __restrict__ out,
                                              int R, int C) {
    __shared__ float tile[64][65];
    const size_t boff = (size_t)blockIdx.z * R * C;
    const float* I = in + boff;
    float* O = out + boff;
    const int c0 = blockIdx.x * 64, r0 = blockIdx.y * 64;
    const int tid = threadIdx.x;
#pragma unroll
    for (int k = 0; k < 4; k++) {
        int idx = k * 256 + tid;
        int row = idx >> 4;
        int c4  = idx & 15;
        float4 v = *reinterpret_cast<const float4*>(I + (size_t)(r0 + row) * C + c0 + 4 * c4);
        tile[row][4 * c4 + 0] = v.x;
        tile[row][4 * c4 + 1] = v.y;
        tile[row][4 * c4 + 2] = v.z;
        tile[row][4 * c4 + 3] = v.w;
    }
    __syncthreads();
#pragma unroll
    for (int k = 0; k < 4; k++) {
        int idx = k * 256 + tid;
        int c  = idx >> 4;
        int r4 = idx & 15;
        float4 v = make_float4(tile[4 * r4 + 0][c], tile[4 * r4 + 1][c],
                               tile[4 * r4 + 2][c], tile[4 * r4 + 3][c]);
        *reinterpret_cast<float4*>(O + (size_t)(c0 + c) * R + r0 + 4 * r4) = v;
    }
}

// t spectrum: block handles channels (2c0, 2c0+1) packed as real+imag of one FFT.
// Scrambled forward FFT -> scatter by true k -> Hermitian unpack -> g_tfft[d][g*512+t].
__global__ void __launch_bounds__(NT, 2) ker_tfft() {
    SW16_DEF;
    extern __shared__ float2 sm[];
    float2* X = sm;
    const int c0 = blockIdx.x;
    const int t = threadIdx.x;
    const int k1 = t >> 5, cc = (t & 31) >> 1, jj = t & 1;
    const float* t0 = g_tT + (size_t)(2 * c0) * N_FFT;
    const float* t1 = t0 + N_FFT;

    float2 a[16], cv[16];
#pragma unroll
    for (int r = 0; r < 16; r++)
        a[r] = make_float2(t0[t + 512 * r], t1[t + 512 * r]);
    fwd8192(X, a, cv, t);

    // scatter Z by true frequency index for the Hermitian cross-reference
    __syncthreads();  // C-phase reads complete in all threads
#pragma unroll
    for (int g = 0; g < 16; g++) {
        int k = k1 + 16 * cc + 256 * g + 4096 * jj;
        X[PADI(k)] = cv[SW16[g]];
    }
    __syncthreads();

    float2* out0 = g_tfft + (size_t)(2 * c0) * N_FFT;
    float2* out1 = g_tfft + (size_t)(2 * c0 + 1) * N_FFT;
#pragma unroll
    for (int g = 0; g < 16; g++) {
        int k = k1 + 16 * cc + 256 * g + 4096 * jj;
        float2 Zk = cv[SW16[g]];
        float2 Zn = X[PADI((N_FFT - k) & (N_FFT - 1))];
        out0[g * 512 + t] = make_float2(0.5f * (Zk.x + Zn.x), 0.5f * (Zk.y - Zn.y));
        out1[g * 512 + t] = make_float2(0.5f * (Zk.y + Zn.y), -0.5f * (Zk.x - Zn.x));
    }
}

// Convolution: one block per (batch-pair, channel). z = x[b0] + i*x[b1].
// Forward (2 exchanges) -> fully register-resident multiply + inverse C2'/C1' ->
// inverse (2 exchanges) -> first-half output straight to gmem.
__global__ void __launch_bounds__(NT, 2) ker_conv() {
    SW16_DEF; DEF_C32; DEF_S32;
    extern __shared__ float2 sm[];
    float2* X = sm;
    const int blk = blockIdx.x;
    const int d = blk & (D_CH - 1);
    const int pr = blk >> 9;
    const int t = threadIdx.x;
    const int k1 = t >> 5, m = t & 31;
    const int cc = (t & 31) >> 1, jj = t & 1;
    const float* x0 = g_xT + ((size_t)(2 * pr) * D_CH + d) * SEQ;
    const float* x1 = x0 + (size_t)D_CH * SEQ;

    float2 a[16], cv[16];
#pragma unroll
    for (int r = 0; r < 8; r++)
        a[r] = make_float2(x0[t + 512 * r], x1[t + 512 * r]);
#pragma unroll
    for (int r = 8; r < 16; r++) a[r] = make_float2(0.0f, 0.0f);
    fwd8192(X, a, cv, t);

    // Middle (all registers): pointwise multiply by tf (scrambled layout) + 1/N,
    // then inverse C2' (shfl radix-2) + pre-twiddle + inverse dft16 over g.
    {
        const float2* tf = g_tfft + (size_t)d * N_FFT;
        const float inv = 1.0f / (float)N_FFT;
        float2 bb[16];
#pragma unroll
        for (int g = 0; g < 16; g++) {
            float2 u = cv[SW16[g]];
            float2 w0 = tf[g * 512 + t];
            float2 o = cmul(u, w0);
            o.x *= inv; o.y *= inv;
            float2 recv;
            recv.x = __shfl_xor_sync(0xffffffffu, o.x, 1);
            recv.y = __shfl_xor_sync(0xffffffffu, o.y, 1);
            if (jj == 0) {
                bb[g] = cadd(o, recv);                 // V0[g] = W[g] + W[g+16]
            } else {
                float2 V = csub(recv, o);              // V1[g] = W[g] - W[g+16]
                bb[g] = cmul(V, make_float2(C32[g], S32[g]));  // * conj(w32^g)
            }
        }
        dft16<true>(bb);   // over g -> b'[j+2h] at bb[SW16[h]]
        __syncthreads();   // all C-phase smem reads done before overwrite
#pragma unroll
        for (int h = 0; h < 16; h++)
            X[PADI(k1 * 512 + 32 * cc + jj + 2 * h)] = bb[SW16[h]];
        __syncthreads();
    }

    // Inverse B': gather over c (stride 32), pre-twiddle conj(w512^{mc}), dft16<true> over c
    {
        float2 r[16];
#pragma unroll
        for (int c = 0; c < 16; c++) r[c] = X[PADI(k1 * 512 + 32 * c + m)];
        float2 w1 = conjf2(g_tw[16 * m]), w8 = conjf2(g_tw[128 * m]);
        float2 w = w1;
#pragma unroll
        for (int c = 1; c < 8; c++) { r[c] = cmul(r[c], w); w = cmul(w, w1); }
        r[8] = cmul(r[8], w8);
        w = cmul(w8, w1);
#pragma unroll
        for (int c = 9; c < 16; c++) { r[c] = cmul(r[c], w); w = cmul(w, w1); }
        dft16<true>(r);    // -> y'[m+32w] at r[SW16[w]]
        __syncthreads();
#pragma unroll
        for (int wL = 0; wL < 16; wL++)
            X[PADI(k1 * 512 + m + 32 * wL)] = r[SW16[wL]];
        __syncthreads();
    }

    // Inverse A': gather over k1 (stride 512), pre-twiddle conj(w^{t*k1}), dft16<true>,
    // keep n1 < 8 (first 4096 samples) -> gmem
    {
        float2 r[16];
#pragma unroll
        for (int k = 0; k < 16; k++) r[k] = X[PADI(k * 512 + t)];
        float2 w1 = conjf2(g_tw[t]), w8 = conjf2(g_tw[8 * t]);
        float2 w = w1;
#pragma unroll
        for (int k = 1; k < 8; k++) { r[k] = cmul(r[k], w); w = cmul(w, w1); }
        r[8] = cmul(r[8], w8);
        w = cmul(w8, w1);
#pragma unroll
        for (int k = 9; k < 16; k++) { r[k] = cmul(r[k], w); w = cmul(w, w1); }
        dft16<true>(r);    // -> x[t+512*n1] at r[SW16[n1]]
        float* o0 = g_oT + ((size_t)(2 * pr) * D_CH + d) * SEQ;
        float* o1 = o0 + (size_t)D_CH * SEQ;
#pragma unroll
        for (int n1 = 0; n1 < 8; n1++) {
            float2 v = r[SW16[n1]];
            o0[t + 512 * n1] = v.x;
            o1[t + 512 * n1] = v.y;
        }
    }
}

extern "C" void kernel_launch(void* const* d_in, const int* in_sizes, int n_in,
                              void* d_out, int out_size) {
    const float* x = (const float*)d_in[0];
    const float* t = (const float*)d_in[1];
    if (n_in >= 2 && in_sizes[0] < in_sizes[1]) {
        const float* tmp = x; x = t; t = tmp;
    }
    float* o = (float*)d_out;

    float* xT;  cudaGetSymbolAddress((void**)&xT, g_xT);
    float* tT;  cudaGetSymbolAddress((void**)&tT, g_tT);
    float* oT;  cudaGetSymbolAddress((void**)&oT, g_oT);

    const size_t smem = (size_t)BUFSZ * sizeof(float2);  // 69632 B -> 2 blocks/SM
    cudaFuncSetAttribute(ker_tfft, cudaFuncAttributeMaxDynamicSharedMemorySize, (int)smem);
    cudaFuncSetAttribute(ker_conv, cudaFuncAttributeMaxDynamicSharedMemorySize, (int)smem);

    ker_tw<<<(N_FFT + 255) / 256, 256>>>();

    {
        dim3 blk(256);
        dim3 gx(D_CH / 64, SEQ / 64, NBATCH);
        ker_T4<<<gx, blk>>>(x, xT, SEQ, D_CH);
        dim3 gt(D_CH / 64, (2 * SEQ) / 64, 1);
        ker_T4<<<gt, blk>>>(t, tT, 2 * SEQ, D_CH);
    }

    ker_tfft<<<D_CH / 2, NT, smem>>>();
    ker_conv<<<2 * D_CH, NT, smem>>>();

    {
        dim3 blk(256);
        dim3 go(SEQ / 64, D_CH / 64, NBATCH);
        ker_T4<<<go, blk>>>(oT, o, D_CH, SEQ);
    }
}

// round 9
// speedup vs baseline: 1.0370x; 1.0370x over previous
#include <cuda_runtime.h>
#include <cstdint>

#define N_FFT 8192
#define NT    512
#define D_CH  512
#define SEQ   4096
#define NBATCH 4

// Padded smem index: +1 float2 every 16
#define PADI(i) ((i) + ((i) >> 4))
#define BUFSZ (N_FFT + (N_FFT >> 4))   // 8704 float2 = 69632 B

__device__ float2 g_tfft[(size_t)D_CH * N_FFT];         // t spectra (33.5 MB)
__device__ float  g_xT[(size_t)NBATCH * D_CH * SEQ];
__device__ float  g_tT[(size_t)D_CH * 2 * SEQ];
__device__ float  g_oT[(size_t)NBATCH * D_CH * SEQ];

__device__ __forceinline__ float2 cadd(float2 a, float2 b) { return make_float2(a.x + b.x, a.y + b.y); }
__device__ __forceinline__ float2 csub(float2 a, float2 b) { return make_float2(a.x - b.x, a.y - b.y); }
__device__ __forceinline__ float2 cmul(float2 a, float2 b) {
    return make_float2(a.x * b.x - a.y * b.y, a.x * b.y + a.y * b.x);
}
template <bool INV>
__device__ __forceinline__ float2 mulJ(float2 z) {
    return INV ? make_float2(-z.y, z.x) : make_float2(z.y, -z.x);
}
template <bool INV>
__device__ __forceinline__ float2 twc(float2 z, float re, float im) {
    float2 w = make_float2(re, INV ? -im : im);
    return cmul(z, w);
}

template <bool INV>
__device__ __forceinline__ void dft4(float2& a0, float2& a1, float2& a2, float2& a3) {
    float2 t0 = cadd(a0, a2), t1 = csub(a0, a2);
    float2 t2 = cadd(a1, a3), t3 = mulJ<INV>(csub(a1, a3));
    a0 = cadd(t0, t2);
    a1 = cadd(t1, t3);
    a2 = csub(t0, t2);
    a3 = csub(t1, t3);
}

template <bool INV>
__device__ __forceinline__ void dft16(float2 a[16]) {
    const float C1 = 0.92387953251128675613f;
    const float S1 = 0.38268343236508977173f;
    const float H  = 0.70710678118654752440f;
#pragma unroll
    for (int ji = 0; ji < 4; ji++) dft4<INV>(a[ji], a[ji + 4], a[ji + 8], a[ji + 12]);
    a[5]  = twc<INV>(a[5],  C1, -S1);
    a[9]  = twc<INV>(a[9],   H,  -H);
    a[13] = twc<INV>(a[13], S1, -C1);
    a[6]  = twc<INV>(a[6],   H,  -H);
    a[10] = mulJ<INV>(a[10]);
    a[14] = twc<INV>(a[14], -H,  -H);
    a[7]  = twc<INV>(a[7],  S1, -C1);
    a[11] = twc<INV>(a[11], -H,  -H);
    a[15] = twc<INV>(a[15], -C1, S1);
#pragma unroll
    for (int ro = 0; ro < 4; ro++) dft4<INV>(a[4 * ro], a[4 * ro + 1], a[4 * ro + 2], a[4 * ro + 3]);
}

// Compute the two base twiddles for a pass inline (no table): w1 = exp(-i*pi*tb/4096),
// w8 = exp(-i*pi*tb/512). Independent of smem; call BEFORE the barrier so the MUFU
// latency overlaps the barrier wait.
template <bool INV>
__device__ __forceinline__ void tw_load(int sLog, int tid, float2& w1, float2& w8) {
    const int tb = (tid >> sLog) << sLog;
    float s1, c1, s8, c8;
    sincospif((float)tb * -(1.0f / 4096.0f), &s1, &c1);
    sincospif((float)tb * -(1.0f / 512.0f),  &s8, &c8);
    w1 = make_float2(c1, INV ? -s1 : s1);
    w8 = make_float2(c8, INV ? -s8 : s8);
}

// Write phase of an in-place radix-16 Stockham pass with preloaded twiddles.
// Output y[r] lands at a[SW16[r]] (base-4 digit swap); local constexpr -> folded.
// Two incremental twiddle chains (from w1 and w8): max serial depth 7.
__device__ __forceinline__ void pass16_write(float2* __restrict__ X, const float2 a[16],
                                             int sLog, int tid, float2 w1, float2 w8) {
    constexpr int SW16[16] = {0,4,8,12, 1,5,9,13, 2,6,10,14, 3,7,11,15};
    const int q = tid & ((1 << sLog) - 1);
    const int p = tid >> sLog;
    const int ob = q + (p << (sLog + 4));
    X[PADI(ob)] = a[SW16[0]];
    float2 w = w1;
#pragma unroll
    for (int r = 1; r < 8; r++) {
        X[PADI(ob + (r << sLog))] = cmul(a[SW16[r]], w);
        w = cmul(w, w1);
    }
    X[PADI(ob + (8 << sLog))] = cmul(a[SW16[8]], w8);
    w = cmul(w8, w1);
#pragma unroll
    for (int r = 9; r < 16; r++) {
        X[PADI(ob + (r << sLog))] = cmul(a[SW16[r]], w);
        w = cmul(w, w1);
    }
}

// Generic in-place pass: read -> dft -> (twiddle calc) -> sync -> write -> sync
template <bool INV>
__device__ __forceinline__ void pass16(float2* __restrict__ X, int sLog, int tid) {
    float2 a[16];
#pragma unroll
    for (int r = 0; r < 16; r++) a[r] = X[PADI(tid + 512 * r)];
    dft16<INV>(a);
    float2 w1, w8;
    tw_load<INV>(sLog, tid, w1, w8);   // overlaps the barrier wait
    __syncthreads();
    pass16_write(X, a, sLog, tid, w1, w8);
    __syncthreads();
}

// ---------------------------------------------------------------------------
// float4 tiled transpose: in[b][r][c] -> out[b][c][r]. 64x64 float tiles, 256 threads.
// R, C multiples of 64. float4 on both gmem sides.
__global__ void __launch_bounds__(256) ker_T4(const float* __restrict__ in, float* __restrict__ out,
                                              int R, int C) {
    __shared__ float tile[64][65];
    const size_t boff = (size_t)blockIdx.z * R * C;
    const float* I = in + boff;
    float* O = out + boff;
    const int c0 = blockIdx.x * 64, r0 = blockIdx.y * 64;
    const int tid = threadIdx.x;
#pragma unroll
    for (int k = 0; k < 4; k++) {
        int idx = k * 256 + tid;           // 0..1023
        int row = idx >> 4;                // 0..63
        int c4  = idx & 15;                // 0..15
        float4 v = *reinterpret_cast<const float4*>(I + (size_t)(r0 + row) * C + c0 + 4 * c4);
        tile[row][4 * c4 + 0] = v.x;
        tile[row][4 * c4 + 1] = v.y;
        tile[row][4 * c4 + 2] = v.z;
        tile[row][4 * c4 + 3] = v.w;
    }
    __syncthreads();
#pragma unroll
    for (int k = 0; k < 4; k++) {
        int idx = k * 256 + tid;
        int c  = idx >> 4;                 // 0..63  (output row = input col)
        int r4 = idx & 15;                 // 0..15  (output col quad)
        float4 v = make_float4(tile[4 * r4 + 0][c], tile[4 * r4 + 1][c],
                               tile[4 * r4 + 2][c], tile[4 * r4 + 3][c]);
        *reinterpret_cast<float4*>(O + (size_t)(c0 + c) * R + r0 + 4 * r4) = v;
    }
}

// t spectrum: block handles channels (2c, 2c+1) as real+imag of one FFT.
// Final radix-2 fused into the Hermitian unpack (computed on the fly).
__global__ void __launch_bounds__(NT, 2) ker_tfft() {
    extern __shared__ float2 sm[];
    float2* X = sm;
    const int c0 = blockIdx.x;
    const int tid = threadIdx.x;
    const float* t0 = g_tT + (size_t)(2 * c0) * N_FFT;
    const float* t1 = t0 + N_FFT;

    {
        float2 a[16];
#pragma unroll
        for (int r = 0; r < 16; r++)
            a[r] = make_float2(t0[tid + 512 * r], t1[tid + 512 * r]);
        dft16<false>(a);
        float2 w1, w8;
        tw_load<false>(0, tid, w1, w8);
        pass16_write(X, a, 0, tid, w1, w8);  // first smem touch: no pre-sync needed
        __syncthreads();
    }
    pass16<false>(X, 4, tid);
    pass16<false>(X, 8, tid);

    // Fused: final radix-2 + Hermitian unpack. Z[k] computed on the fly from Y:
    //   k < 4096: Z[k] = Y[k] + Y[k+4096];  k >= 4096: Z[k] = Y[k-4096] - Y[k]
    float2* out0 = g_tfft + (size_t)(2 * c0) * N_FFT;
    float2* out1 = g_tfft + (size_t)(2 * c0 + 1) * N_FFT;
#pragma unroll
    for (int i = 0; i < 16; i++) {
        int k = tid + 512 * i;
        int kl = k & 4095;
        float2 ua = X[PADI(kl)], ub = X[PADI(kl + 4096)];
        float2 Zk = (k < 4096) ? cadd(ua, ub) : csub(ua, ub);
        int kn = (N_FFT - k) & (N_FFT - 1);
        int knl = kn & 4095;
        float2 va = X[PADI(knl)], vb = X[PADI(knl + 4096)];
        float2 Zn = (kn < 4096) ? cadd(va, vb) : csub(va, vb);
        out0[k] = make_float2(0.5f * (Zk.x + Zn.x), 0.5f * (Zk.y - Zn.y));
        out1[k] = make_float2(0.5f * (Zk.y + Zn.y), -0.5f * (Zk.x - Zn.x));
    }
}

// Convolution: one block per (batch-pair, channel). z = x[b0] + i*x[b1].
__global__ void __launch_bounds__(NT, 2) ker_conv() {
    extern __shared__ float2 sm[];
    float2* X = sm;
    const int blk = blockIdx.x;
    const int d = blk & (D_CH - 1);
    const int pr = blk >> 9;
    const int tid = threadIdx.x;
    const float* x0 = g_xT + ((size_t)(2 * pr) * D_CH + d) * SEQ;
    const float* x1 = x0 + (size_t)D_CH * SEQ;

    // forward pass 0 fused with gmem load (zero-pad r>=8)
    {
        float2 a[16];
#pragma unroll
        for (int r = 0; r < 8; r++)
            a[r] = make_float2(x0[tid + 512 * r], x1[tid + 512 * r]);
#pragma unroll
        for (int r = 8; r < 16; r++) a[r] = make_float2(0.0f, 0.0f);
        dft16<false>(a);
        float2 w1, w8;
        tw_load<false>(0, tid, w1, w8);
        pass16_write(X, a, 0, tid, w1, w8);
        __syncthreads();
    }
    pass16<false>(X, 4, tid);
    pass16<false>(X, 8, tid);

    // Fused: forward final radix-2 + pointwise multiply (+1/N) + inverse pass 0.
    // Thread's radix-2 pairs (q, q+4096), q = tid+512i, are exactly the 16 inputs
    // tid+512r of its inverse radix-16 butterfly -> do it all in registers.
    {
        const float2* tf = g_tfft + (size_t)d * N_FFT;
        const float inv = 1.0f / (float)N_FFT;
        float2 a[16];
#pragma unroll
        for (int i = 0; i < 8; i++) {
            int q = tid + 512 * i;
            float2 u = X[PADI(q)];
            float2 v = X[PADI(q + 4096)];
            float2 s = cmul(cadd(u, v), tf[q]);
            float2 dd = cmul(csub(u, v), tf[q + 4096]);
            a[i]     = make_float2(s.x * inv, s.y * inv);
            a[i + 8] = make_float2(dd.x * inv, dd.y * inv);
        }
        dft16<true>(a);
        float2 w1, w8;
        tw_load<true>(0, tid, w1, w8);
        __syncthreads();
        pass16_write(X, a, 0, tid, w1, w8);
        __syncthreads();
    }
    pass16<true>(X, 4, tid);
    pass16<true>(X, 8, tid);

    // final radix-2 of inverse: only first half needed -> sum only, straight to gmem
    float* o0 = g_oT + ((size_t)(2 * pr) * D_CH + d) * SEQ;
    float* o1 = o0 + (size_t)D_CH * SEQ;
#pragma unroll
    for (int i = 0; i < 8; i++) {
        int q = tid + 512 * i;
        float2 s = cadd(X[PADI(q)], X[PADI(q + 4096)]);
        o0[q] = s.x;
        o1[q] = s.y;
    }
}

extern "C" void kernel_launch(void* const* d_in, const int* in_sizes, int n_in,
                              void* d_out, int out_size) {
    const float* x = (const float*)d_in[0];
    const float* t = (const float*)d_in[1];
    if (n_in >= 2 && in_sizes[0] < in_sizes[1]) {
        const float* tmp = x; x = t; t = tmp;
    }
    float* o = (float*)d_out;

    float* xT;  cudaGetSymbolAddress((void**)&xT, g_xT);
    float* tT;  cudaGetSymbolAddress((void**)&tT, g_tT);
    float* oT;  cudaGetSymbolAddress((void**)&oT, g_oT);

    const size_t smem = (size_t)BUFSZ * sizeof(float2);  // 69632 B -> 2 blocks/SM
    cudaFuncSetAttribute(ker_tfft, cudaFuncAttributeMaxDynamicSharedMemorySize, (int)smem);
    cudaFuncSetAttribute(ker_conv, cudaFuncAttributeMaxDynamicSharedMemorySize, (int)smem);

    {
        dim3 blk(256);
        dim3 gt(D_CH / 64, (2 * SEQ) / 64, 1);
        ker_T4<<<gt, blk>>>(t, tT, 2 * SEQ, D_CH);
        dim3 gx(D_CH / 64, SEQ / 64, NBATCH);
        ker_T4<<<gx, blk>>>(x, xT, SEQ, D_CH);
    }

    ker_tfft<<<D_CH / 2, NT, smem>>>();
    ker_conv<<<2 * D_CH, NT, smem>>>();

    {
        dim3 blk(256);
        dim3 go(SEQ / 64, D_CH / 64, NBATCH);
        ker_T4<<<go, blk>>>(oT, o, D_CH, SEQ);
    }
}

// round 10
// speedup vs baseline: 1.0569x; 1.0192x over previous
#include <cuda_runtime.h>
#include <cstdint>

#define N_FFT 8192
#define NT    512
#define D_CH  512
#define SEQ   4096
#define NBATCH 4

// Padded smem index: +1 float2 every 16
#define PADI(i) ((i) + ((i) >> 4))
#define BUFSZ (N_FFT + (N_FFT >> 4))   // 8704 float2 = 69632 B

__device__ float2 g_tw[N_FFT];                          // exp(-2*pi*i*k/N)
__device__ float2 g_tfft[(size_t)D_CH * N_FFT];         // t spectra (33.5 MB)
__device__ float  g_xT[(size_t)NBATCH * D_CH * SEQ];
__device__ float  g_tT[(size_t)D_CH * 2 * SEQ];
__device__ float  g_oT[(size_t)NBATCH * D_CH * SEQ];

__device__ __forceinline__ float2 cadd(float2 a, float2 b) { return make_float2(a.x + b.x, a.y + b.y); }
__device__ __forceinline__ float2 csub(float2 a, float2 b) { return make_float2(a.x - b.x, a.y - b.y); }
__device__ __forceinline__ float2 cmul(float2 a, float2 b) {
    return make_float2(a.x * b.x - a.y * b.y, a.x * b.y + a.y * b.x);
}
template <bool INV>
__device__ __forceinline__ float2 mulJ(float2 z) {
    return INV ? make_float2(-z.y, z.x) : make_float2(z.y, -z.x);
}
template <bool INV>
__device__ __forceinline__ float2 twc(float2 z, float re, float im) {
    float2 w = make_float2(re, INV ? -im : im);
    return cmul(z, w);
}

template <bool INV>
__device__ __forceinline__ void dft4(float2& a0, float2& a1, float2& a2, float2& a3) {
    float2 t0 = cadd(a0, a2), t1 = csub(a0, a2);
    float2 t2 = cadd(a1, a3), t3 = mulJ<INV>(csub(a1, a3));
    a0 = cadd(t0, t2);
    a1 = cadd(t1, t3);
    a2 = csub(t0, t2);
    a3 = csub(t1, t3);
}

template <bool INV>
__device__ __forceinline__ void dft16(float2 a[16]) {
    const float C1 = 0.92387953251128675613f;
    const float S1 = 0.38268343236508977173f;
    const float H  = 0.70710678118654752440f;
#pragma unroll
    for (int ji = 0; ji < 4; ji++) dft4<INV>(a[ji], a[ji + 4], a[ji + 8], a[ji + 12]);
    a[5]  = twc<INV>(a[5],  C1, -S1);
    a[9]  = twc<INV>(a[9],   H,  -H);
    a[13] = twc<INV>(a[13], S1, -C1);
    a[6]  = twc<INV>(a[6],   H,  -H);
    a[10] = mulJ<INV>(a[10]);
    a[14] = twc<INV>(a[14], -H,  -H);
    a[7]  = twc<INV>(a[7],  S1, -C1);
    a[11] = twc<INV>(a[11], -H,  -H);
    a[15] = twc<INV>(a[15], -C1, S1);
#pragma unroll
    for (int ro = 0; ro < 4; ro++) dft4<INV>(a[4 * ro], a[4 * ro + 1], a[4 * ro + 2], a[4 * ro + 3]);
}

// Load the two base twiddles for a pass (independent of smem; call BEFORE the barrier)
template <bool INV>
__device__ __forceinline__ void tw_load(int sLog, int tid, float2& w1, float2& w8) {
    const int tb = (tid >> sLog) << sLog;
    w1 = g_tw[tb];
    w8 = g_tw[tb << 3];
    if (INV) { w1.y = -w1.y; w8.y = -w8.y; }
}

// Write phase of an in-place radix-16 Stockham pass with preloaded twiddles.
// Output y[r] lands at a[SW16[r]] (base-4 digit swap); local constexpr -> folded.
// Two incremental twiddle chains (from w1 and w8): max serial depth 7.
__device__ __forceinline__ void pass16_write(float2* __restrict__ X, const float2 a[16],
                                             int sLog, int tid, float2 w1, float2 w8) {
    constexpr int SW16[16] = {0,4,8,12, 1,5,9,13, 2,6,10,14, 3,7,11,15};
    const int q = tid & ((1 << sLog) - 1);
    const int p = tid >> sLog;
    const int ob = q + (p << (sLog + 4));
    X[PADI(ob)] = a[SW16[0]];
    float2 w = w1;
#pragma unroll
    for (int r = 1; r < 8; r++) {
        X[PADI(ob + (r << sLog))] = cmul(a[SW16[r]], w);
        w = cmul(w, w1);
    }
    X[PADI(ob + (8 << sLog))] = cmul(a[SW16[8]], w8);
    w = cmul(w8, w1);
#pragma unroll
    for (int r = 9; r < 16; r++) {
        X[PADI(ob + (r << sLog))] = cmul(a[SW16[r]], w);
        w = cmul(w, w1);
    }
}

// Generic in-place pass: read -> dft -> (twiddle loads) -> sync -> write -> sync
template <bool INV>
__device__ __forceinline__ void pass16(float2* __restrict__ X, int sLog, int tid) {
    float2 a[16];
#pragma unroll
    for (int r = 0; r < 16; r++) a[r] = X[PADI(tid + 512 * r)];
    dft16<INV>(a);
    float2 w1, w8;
    tw_load<INV>(sLog, tid, w1, w8);   // overlaps the barrier wait
    __syncthreads();
    pass16_write(X, a, sLog, tid, w1, w8);
    __syncthreads();
}

// ---------------------------------------------------------------------------
// float4 tiled transpose: in[b][r][c] -> out[b][c][r]. 64x64 float tiles, 256 threads.
// If fill_tw != 0, the first 32 blocks (flat id) also populate g_tw (8192 entries)
// using otherwise-idle ALU time in this DRAM-bound kernel.
__global__ void __launch_bounds__(256) ker_T4(const float* __restrict__ in, float* __restrict__ out,
                                              int R, int C, int fill_tw) {
    __shared__ float tile[64][65];
    if (fill_tw && blockIdx.z == 0) {
        int fb = blockIdx.x + blockIdx.y * gridDim.x;
        if (fb < 32) {
            int k = fb * 256 + threadIdx.x;
            float s, c;
            sincospif(-2.0f * (float)k / (float)N_FFT, &s, &c);
            g_tw[k] = make_float2(c, s);
        }
    }
    const size_t boff = (size_t)blockIdx.z * R * C;
    const float* I = in + boff;
    float* O = out + boff;
    const int c0 = blockIdx.x * 64, r0 = blockIdx.y * 64;
    const int tid = threadIdx.x;
#pragma unroll
    for (int k = 0; k < 4; k++) {
        int idx = k * 256 + tid;           // 0..1023
        int row = idx >> 4;                // 0..63
        int c4  = idx & 15;                // 0..15
        float4 v = *reinterpret_cast<const float4*>(I + (size_t)(r0 + row) * C + c0 + 4 * c4);
        tile[row][4 * c4 + 0] = v.x;
        tile[row][4 * c4 + 1] = v.y;
        tile[row][4 * c4 + 2] = v.z;
        tile[row][4 * c4 + 3] = v.w;
    }
    __syncthreads();
#pragma unroll
    for (int k = 0; k < 4; k++) {
        int idx = k * 256 + tid;
        int c  = idx >> 4;                 // 0..63  (output row = input col)
        int r4 = idx & 15;                 // 0..15  (output col quad)
        float4 v = make_float4(tile[4 * r4 + 0][c], tile[4 * r4 + 1][c],
                               tile[4 * r4 + 2][c], tile[4 * r4 + 3][c]);
        *reinterpret_cast<float4*>(O + (size_t)(c0 + c) * R + r0 + 4 * r4) = v;
    }
}

// t spectrum: block handles channels (2c, 2c+1) as real+imag of one FFT.
// Final radix-2 fused into the Hermitian unpack (computed on the fly).
__global__ void __launch_bounds__(NT, 2) ker_tfft() {
    extern __shared__ float2 sm[];
    float2* X = sm;
    const int c0 = blockIdx.x;
    const int tid = threadIdx.x;
    const float* t0 = g_tT + (size_t)(2 * c0) * N_FFT;
    const float* t1 = t0 + N_FFT;

    {
        float2 a[16];
#pragma unroll
        for (int r = 0; r < 16; r++)
            a[r] = make_float2(t0[tid + 512 * r], t1[tid + 512 * r]);
        dft16<false>(a);
        float2 w1, w8;
        tw_load<false>(0, tid, w1, w8);
        pass16_write(X, a, 0, tid, w1, w8);  // first smem touch: no pre-sync needed
        __syncthreads();
    }
    pass16<false>(X, 4, tid);
    pass16<false>(X, 8, tid);

    // Fused: final radix-2 + Hermitian unpack. Z[k] computed on the fly from Y:
    //   k < 4096: Z[k] = Y[k] + Y[k+4096];  k >= 4096: Z[k] = Y[k-4096] - Y[k]
    float2* out0 = g_tfft + (size_t)(2 * c0) * N_FFT;
    float2* out1 = g_tfft + (size_t)(2 * c0 + 1) * N_FFT;
#pragma unroll
    for (int i = 0; i < 16; i++) {
        int k = tid + 512 * i;
        int kl = k & 4095;
        float2 ua = X[PADI(kl)], ub = X[PADI(kl + 4096)];
        float2 Zk = (k < 4096) ? cadd(ua, ub) : csub(ua, ub);
        int kn = (N_FFT - k) & (N_FFT - 1);
        int knl = kn & 4095;
        float2 va = X[PADI(knl)], vb = X[PADI(knl + 4096)];
        float2 Zn = (kn < 4096) ? cadd(va, vb) : csub(va, vb);
        out0[k] = make_float2(0.5f * (Zk.x + Zn.x), 0.5f * (Zk.y - Zn.y));
        out1[k] = make_float2(0.5f * (Zk.y + Zn.y), -0.5f * (Zk.x - Zn.x));
    }
}

// Convolution: one block per (batch-pair, channel). z = x[b0] + i*x[b1].
__global__ void __launch_bounds__(NT, 2) ker_conv() {
    extern __shared__ float2 sm[];
    float2* X = sm;
    const int blk = blockIdx.x;
    const int d = blk & (D_CH - 1);
    const int pr = blk >> 9;
    const int tid = threadIdx.x;
    const float* x0 = g_xT + ((size_t)(2 * pr) * D_CH + d) * SEQ;
    const float* x1 = x0 + (size_t)D_CH * SEQ;

    // forward pass 0 fused with gmem load (zero-pad r>=8)
    {
        float2 a[16];
#pragma unroll
        for (int r = 0; r < 8; r++)
            a[r] = make_float2(x0[tid + 512 * r], x1[tid + 512 * r]);
#pragma unroll
        for (int r = 8; r < 16; r++) a[r] = make_float2(0.0f, 0.0f);
        dft16<false>(a);
        float2 w1, w8;
        tw_load<false>(0, tid, w1, w8);
        pass16_write(X, a, 0, tid, w1, w8);
        __syncthreads();
    }
    pass16<false>(X, 4, tid);
    pass16<false>(X, 8, tid);

    // Fused: forward final radix-2 + pointwise multiply (+1/N) + inverse pass 0.
    // Thread's radix-2 pairs (q, q+4096), q = tid+512i, are exactly the 16 inputs
    // tid+512r of its inverse radix-16 butterfly -> do it all in registers.
    {
        const float2* tf = g_tfft + (size_t)d * N_FFT;
        const float inv = 1.0f / (float)N_FFT;
        float2 a[16];
#pragma unroll
        for (int i = 0; i < 8; i++) {
            int q = tid + 512 * i;
            float2 u = X[PADI(q)];
            float2 v = X[PADI(q + 4096)];
            float2 s = cmul(cadd(u, v), tf[q]);
            float2 dd = cmul(csub(u, v), tf[q + 4096]);
            a[i]     = make_float2(s.x * inv, s.y * inv);
            a[i + 8] = make_float2(dd.x * inv, dd.y * inv);
        }
        dft16<true>(a);
        float2 w1, w8;
        tw_load<true>(0, tid, w1, w8);
        __syncthreads();
        pass16_write(X, a, 0, tid, w1, w8);
        __syncthreads();
    }
    pass16<true>(X, 4, tid);
    pass16<true>(X, 8, tid);

    // final radix-2 of inverse: only first half needed -> sum only, straight to gmem
    float* o0 = g_oT + ((size_t)(2 * pr) * D_CH + d) * SEQ;
    float* o1 = o0 + (size_t)D_CH * SEQ;
#pragma unroll
    for (int i = 0; i < 8; i++) {
        int q = tid + 512 * i;
        float2 s = cadd(X[PADI(q)], X[PADI(q + 4096)]);
        o0[q] = s.x;
        o1[q] = s.y;
    }
}

extern "C" void kernel_launch(void* const* d_in, const int* in_sizes, int n_in,
                              void* d_out, int out_size) {
    const float* x = (const float*)d_in[0];
    const float* t = (const float*)d_in[1];
    if (n_in >= 2 && in_sizes[0] < in_sizes[1]) {
        const float* tmp = x; x = t; t = tmp;
    }
    float* o = (float*)d_out;

    float* xT;  cudaGetSymbolAddress((void**)&xT, g_xT);
    float* tT;  cudaGetSymbolAddress((void**)&tT, g_tT);
    float* oT;  cudaGetSymbolAddress((void**)&oT, g_oT);

    const size_t smem = (size_t)BUFSZ * sizeof(float2);  // 69632 B -> 2 blocks/SM
    cudaFuncSetAttribute(ker_tfft, cudaFuncAttributeMaxDynamicSharedMemorySize, (int)smem);
    cudaFuncSetAttribute(ker_conv, cudaFuncAttributeMaxDynamicSharedMemorySize, (int)smem);

    {
        dim3 blk(256);
        // t transpose also fills the twiddle table (completes before ker_tfft starts)
        dim3 gt(D_CH / 64, (2 * SEQ) / 64, 1);
        ker_T4<<<gt, blk>>>(t, tT, 2 * SEQ, D_CH, 1);
        dim3 gx(D_CH / 64, SEQ / 64, NBATCH);
        ker_T4<<<gx, blk>>>(x, xT, SEQ, D_CH, 0);
    }

    ker_tfft<<<D_CH / 2, NT, smem>>>();
    ker_conv<<<2 * D_CH, NT, smem>>>();

    {
        dim3 blk(256);
        dim3 go(SEQ / 64, D_CH / 64, NBATCH);
        ker_T4<<<go, blk>>>(oT, o, D_CH, SEQ, 0);
    }
}

// round 11
// speedup vs baseline: 1.0870x; 1.0285x over previous
#include <cuda_runtime.h>
#include <cstdint>

#define N_FFT 8192
#define NT    512
#define D_CH  512
#define SEQ   4096
#define NBATCH 4

// Padded smem index: +1 float2 every 16
#define PADI(i) ((i) + ((i) >> 4))
#define BUFSZ (N_FFT + (N_FFT >> 4))   // 8704 float2 = 69632 B

__device__ float2 g_tw[N_FFT];                          // exp(-2*pi*i*k/N)
__device__ float2 g_tfft[(size_t)D_CH * N_FFT];         // t spectra (33.5 MB)
__device__ float  g_xT[(size_t)NBATCH * D_CH * SEQ];
__device__ float  g_tT[(size_t)D_CH * 2 * SEQ];
__device__ float  g_oT[(size_t)NBATCH * D_CH * SEQ];

__device__ __forceinline__ float2 cadd(float2 a, float2 b) { return make_float2(a.x + b.x, a.y + b.y); }
__device__ __forceinline__ float2 csub(float2 a, float2 b) { return make_float2(a.x - b.x, a.y - b.y); }
__device__ __forceinline__ float2 cmul(float2 a, float2 b) {
    return make_float2(a.x * b.x - a.y * b.y, a.x * b.y + a.y * b.x);
}
template <bool INV>
__device__ __forceinline__ float2 mulJ(float2 z) {
    return INV ? make_float2(-z.y, z.x) : make_float2(z.y, -z.x);
}
template <bool INV>
__device__ __forceinline__ float2 twc(float2 z, float re, float im) {
    float2 w = make_float2(re, INV ? -im : im);
    return cmul(z, w);
}

template <bool INV>
__device__ __forceinline__ void dft4(float2& a0, float2& a1, float2& a2, float2& a3) {
    float2 t0 = cadd(a0, a2), t1 = csub(a0, a2);
    float2 t2 = cadd(a1, a3), t3 = mulJ<INV>(csub(a1, a3));
    a0 = cadd(t0, t2);
    a1 = cadd(t1, t3);
    a2 = csub(t0, t2);
    a3 = csub(t1, t3);
}

template <bool INV>
__device__ __forceinline__ void dft16(float2 a[16]) {
    const float C1 = 0.92387953251128675613f;
    const float S1 = 0.38268343236508977173f;
    const float H  = 0.70710678118654752440f;
#pragma unroll
    for (int ji = 0; ji < 4; ji++) dft4<INV>(a[ji], a[ji + 4], a[ji + 8], a[ji + 12]);
    a[5]  = twc<INV>(a[5],  C1, -S1);
    a[9]  = twc<INV>(a[9],   H,  -H);
    a[13] = twc<INV>(a[13], S1, -C1);
    a[6]  = twc<INV>(a[6],   H,  -H);
    a[10] = mulJ<INV>(a[10]);
    a[14] = twc<INV>(a[14], -H,  -H);
    a[7]  = twc<INV>(a[7],  S1, -C1);
    a[11] = twc<INV>(a[11], -H,  -H);
    a[15] = twc<INV>(a[15], -C1, S1);
#pragma unroll
    for (int ro = 0; ro < 4; ro++) dft4<INV>(a[4 * ro], a[4 * ro + 1], a[4 * ro + 2], a[4 * ro + 3]);
}

// Load the two base twiddles for a pass (independent of smem; call BEFORE the barrier)
template <bool INV>
__device__ __forceinline__ void tw_load(int sLog, int tid, float2& w1, float2& w8) {
    const int tb = (tid >> sLog) << sLog;
    w1 = g_tw[tb];
    w8 = g_tw[tb << 3];
    if (INV) { w1.y = -w1.y; w8.y = -w8.y; }
}

// Write phase of an in-place radix-16 Stockham pass with preloaded twiddles.
__device__ __forceinline__ void pass16_write(float2* __restrict__ X, const float2 a[16],
                                             int sLog, int tid, float2 w1, float2 w8) {
    constexpr int SW16[16] = {0,4,8,12, 1,5,9,13, 2,6,10,14, 3,7,11,15};
    const int q = tid & ((1 << sLog) - 1);
    const int p = tid >> sLog;
    const int ob = q + (p << (sLog + 4));
    X[PADI(ob)] = a[SW16[0]];
    float2 w = w1;
#pragma unroll
    for (int r = 1; r < 8; r++) {
        X[PADI(ob + (r << sLog))] = cmul(a[SW16[r]], w);
        w = cmul(w, w1);
    }
    X[PADI(ob + (8 << sLog))] = cmul(a[SW16[8]], w8);
    w = cmul(w8, w1);
#pragma unroll
    for (int r = 9; r < 16; r++) {
        X[PADI(ob + (r << sLog))] = cmul(a[SW16[r]], w);
        w = cmul(w, w1);
    }
}

// Generic in-place pass: read -> dft -> (twiddle loads) -> sync -> write -> sync
template <bool INV>
__device__ __forceinline__ void pass16(float2* __restrict__ X, int sLog, int tid) {
    float2 a[16];
#pragma unroll
    for (int r = 0; r < 16; r++) a[r] = X[PADI(tid + 512 * r)];
    dft16<INV>(a);
    float2 w1, w8;
    tw_load<INV>(sLog, tid, w1, w8);   // overlaps the barrier wait
    __syncthreads();
    pass16_write(X, a, sLog, tid, w1, w8);
    __syncthreads();
}

// ---------------------------------------------------------------------------
// float4 tiled transpose (256 threads): in[b][r][c] -> out[b][c][r]. 64x64 tiles.
// If fill_tw != 0, the first 32 blocks also populate g_tw.
__global__ void __launch_bounds__(256) ker_T4(const float* __restrict__ in, float* __restrict__ out,
                                              int R, int C, int fill_tw) {
    __shared__ float tile[64][65];
    if (fill_tw && blockIdx.z == 0) {
        int fb = blockIdx.x + blockIdx.y * gridDim.x;
        if (fb < 32) {
            int k = fb * 256 + threadIdx.x;
            float s, c;
            sincospif(-2.0f * (float)k / (float)N_FFT, &s, &c);
            g_tw[k] = make_float2(c, s);
        }
    }
    const size_t boff = (size_t)blockIdx.z * R * C;
    const float* I = in + boff;
    float* O = out + boff;
    const int c0 = blockIdx.x * 64, r0 = blockIdx.y * 64;
    const int tid = threadIdx.x;
#pragma unroll
    for (int k = 0; k < 4; k++) {
        int idx = k * 256 + tid;
        int row = idx >> 4;
        int c4  = idx & 15;
        float4 v = *reinterpret_cast<const float4*>(I + (size_t)(r0 + row) * C + c0 + 4 * c4);
        tile[row][4 * c4 + 0] = v.x;
        tile[row][4 * c4 + 1] = v.y;
        tile[row][4 * c4 + 2] = v.z;
        tile[row][4 * c4 + 3] = v.w;
    }
    __syncthreads();
#pragma unroll
    for (int k = 0; k < 4; k++) {
        int idx = k * 256 + tid;
        int c  = idx >> 4;
        int r4 = idx & 15;
        float4 v = make_float4(tile[4 * r4 + 0][c], tile[4 * r4 + 1][c],
                               tile[4 * r4 + 2][c], tile[4 * r4 + 3][c]);
        *reinterpret_cast<float4*>(O + (size_t)(c0 + c) * R + r0 + 4 * r4) = v;
    }
}

// Fat kernel: blocks [0,256) compute the t spectra (tfft); blocks [256,2304)
// transpose x (b,4096,512) -> xT (b,512,4096) in 64x64 tiles with 512 threads.
// The two halves are independent and overlap on the SMs.
__global__ void __launch_bounds__(NT, 2) ker_xT_tfft(const float* __restrict__ x) {
    extern __shared__ float2 sm[];
    const int tid = threadIdx.x;

    if (blockIdx.x >= 256) {
        // ---- x transpose tile ----
        float* tile = reinterpret_cast<float*>(sm);   // used as [64][65]
        const int tt = blockIdx.x - 256;              // 0..2047
        const int b = tt >> 9;
        const int rem = tt & 511;
        const int c0 = (rem & 7) * 64;                // channel tile (C=512)
        const int r0 = (rem >> 3) * 64;               // seq tile (R=4096)
        const float* I = x + (size_t)b * SEQ * D_CH;
        float* O = g_xT + (size_t)b * SEQ * D_CH;
#pragma unroll
        for (int k = 0; k < 2; k++) {
            int idx = k * 512 + tid;                  // 0..1023
            int row = idx >> 4, c4 = idx & 15;
            float4 v = *reinterpret_cast<const float4*>(I + (size_t)(r0 + row) * D_CH + c0 + 4 * c4);
            tile[row * 65 + 4 * c4 + 0] = v.x;
            tile[row * 65 + 4 * c4 + 1] = v.y;
            tile[row * 65 + 4 * c4 + 2] = v.z;
            tile[row * 65 + 4 * c4 + 3] = v.w;
        }
        __syncthreads();
#pragma unroll
        for (int k = 0; k < 2; k++) {
            int idx = k * 512 + tid;
            int c = idx >> 4, r4 = idx & 15;
            float4 v = make_float4(tile[(4 * r4 + 0) * 65 + c], tile[(4 * r4 + 1) * 65 + c],
                                   tile[(4 * r4 + 2) * 65 + c], tile[(4 * r4 + 3) * 65 + c]);
            *reinterpret_cast<float4*>(O + (size_t)(c0 + c) * SEQ + r0 + 4 * r4) = v;
        }
        return;
    }

    // ---- tfft: block handles channels (2c0, 2c0+1) as real+imag of one FFT ----
    float2* X = sm;
    const int c0 = blockIdx.x;
    const float* t0 = g_tT + (size_t)(2 * c0) * N_FFT;
    const float* t1 = t0 + N_FFT;

    {
        float2 a[16];
#pragma unroll
        for (int r = 0; r < 16; r++)
            a[r] = make_float2(t0[tid + 512 * r], t1[tid + 512 * r]);
        dft16<false>(a);
        float2 w1, w8;
        tw_load<false>(0, tid, w1, w8);
        pass16_write(X, a, 0, tid, w1, w8);  // first smem touch: no pre-sync needed
        __syncthreads();
    }
    pass16<false>(X, 4, tid);
    pass16<false>(X, 8, tid);

    // Fused: final radix-2 + Hermitian unpack on the fly.
    float2* out0 = g_tfft + (size_t)(2 * c0) * N_FFT;
    float2* out1 = g_tfft + (size_t)(2 * c0 + 1) * N_FFT;
#pragma unroll
    for (int i = 0; i < 16; i++) {
        int k = tid + 512 * i;
        int kl = k & 4095;
        float2 ua = X[PADI(kl)], ub = X[PADI(kl + 4096)];
        float2 Zk = (k < 4096) ? cadd(ua, ub) : csub(ua, ub);
        int kn = (N_FFT - k) & (N_FFT - 1);
        int knl = kn & 4095;
        float2 va = X[PADI(knl)], vb = X[PADI(knl + 4096)];
        float2 Zn = (kn < 4096) ? cadd(va, vb) : csub(va, vb);
        out0[k] = make_float2(0.5f * (Zk.x + Zn.x), 0.5f * (Zk.y - Zn.y));
        out1[k] = make_float2(0.5f * (Zk.y + Zn.y), -0.5f * (Zk.x - Zn.x));
    }
}

// Convolution: one block per (batch-pair, channel). z = x[b0] + i*x[b1].
__global__ void __launch_bounds__(NT, 2) ker_conv() {
    extern __shared__ float2 sm[];
    float2* X = sm;
    const int blk = blockIdx.x;
    const int d = blk & (D_CH - 1);
    const int pr = blk >> 9;
    const int tid = threadIdx.x;
    const float* x0 = g_xT + ((size_t)(2 * pr) * D_CH + d) * SEQ;
    const float* x1 = x0 + (size_t)D_CH * SEQ;

    // forward pass 0 fused with gmem load (zero-pad r>=8)
    {
        float2 a[16];
#pragma unroll
        for (int r = 0; r < 8; r++)
            a[r] = make_float2(x0[tid + 512 * r], x1[tid + 512 * r]);
#pragma unroll
        for (int r = 8; r < 16; r++) a[r] = make_float2(0.0f, 0.0f);
        dft16<false>(a);
        float2 w1, w8;
        tw_load<false>(0, tid, w1, w8);
        pass16_write(X, a, 0, tid, w1, w8);
        __syncthreads();
    }
    pass16<false>(X, 4, tid);
    pass16<false>(X, 8, tid);

    // Fused: forward final radix-2 + pointwise multiply (+1/N) + inverse pass 0.
    {
        const float2* tf = g_tfft + (size_t)d * N_FFT;
        const float inv = 1.0f / (float)N_FFT;
        float2 a[16];
#pragma unroll
        for (int i = 0; i < 8; i++) {
            int q = tid + 512 * i;
            float2 u = X[PADI(q)];
            float2 v = X[PADI(q + 4096)];
            float2 s = cmul(cadd(u, v), tf[q]);
            float2 dd = cmul(csub(u, v), tf[q + 4096]);
            a[i]     = make_float2(s.x * inv, s.y * inv);
            a[i + 8] = make_float2(dd.x * inv, dd.y * inv);
        }
        dft16<true>(a);
        float2 w1, w8;
        tw_load<true>(0, tid, w1, w8);
        __syncthreads();
        pass16_write(X, a, 0, tid, w1, w8);
        __syncthreads();
    }
    pass16<true>(X, 4, tid);
    pass16<true>(X, 8, tid);

    // final radix-2 of inverse: only first half needed -> sum only, straight to gmem
    float* o0 = g_oT + ((size_t)(2 * pr) * D_CH + d) * SEQ;
    float* o1 = o0 + (size_t)D_CH * SEQ;
#pragma unroll
    for (int i = 0; i < 8; i++) {
        int q = tid + 512 * i;
        float2 s = cadd(X[PADI(q)], X[PADI(q + 4096)]);
        o0[q] = s.x;
        o1[q] = s.y;
    }
}

extern "C" void kernel_launch(void* const* d_in, const int* in_sizes, int n_in,
                              void* d_out, int out_size) {
    const float* x = (const float*)d_in[0];
    const float* t = (const float*)d_in[1];
    if (n_in >= 2 && in_sizes[0] < in_sizes[1]) {
        const float* tmp = x; x = t; t = tmp;
    }
    float* o = (float*)d_out;

    float* tT;  cudaGetSymbolAddress((void**)&tT, g_tT);
    float* oT;  cudaGetSymbolAddress((void**)&oT, g_oT);

    const size_t smem = (size_t)BUFSZ * sizeof(float2);  // 69632 B -> 2 blocks/SM
    cudaFuncSetAttribute(ker_xT_tfft, cudaFuncAttributeMaxDynamicSharedMemorySize, (int)smem);
    cudaFuncSetAttribute(ker_conv, cudaFuncAttributeMaxDynamicSharedMemorySize, (int)smem);

    {
        dim3 blk(256);
        // t transpose also fills the twiddle table (completes before ker_xT_tfft starts)
        dim3 gt(D_CH / 64, (2 * SEQ) / 64, 1);
        ker_T4<<<gt, blk>>>(t, tT, 2 * SEQ, D_CH, 1);
    }

    // Fused: t-spectra FFTs (blocks 0..255) overlapped with x transpose (blocks 256..2303)
    ker_xT_tfft<<<256 + 2048, NT, smem>>>(x);

    ker_conv<<<2 * D_CH, NT, smem>>>();

    {
        dim3 blk(256);
        dim3 go(SEQ / 64, D_CH / 64, NBATCH);
        ker_T4<<<go, blk>>>(oT, o, D_CH, SEQ, 0);
    }
}